// round 14
// baseline (speedup 1.0000x reference)
#include <cuda_runtime.h>
#include <cuda_fp16.h>
#include <math.h>
#include <stdint.h>

#define DN 128
#define TILE 64
#define NSLOT 96

// ---- scratch (no allocations allowed) ----
__device__ float g_qry[512 * DN];   // stored pre-scaled by 0.5
__device__ int   g_start[513];
__device__ float g_acc[512 * NSLOT * DN];
__device__ float g_ws[512 * NSLOT];

__device__ __forceinline__ unsigned f2tf(float x) {
    unsigned r;
    asm("cvt.rna.tf32.f32 %0, %1;" : "=r"(r) : "f"(x));
    return r;
}
#define GBAR(id) asm volatile("bar.sync %0, 256;" :: "r"(id) : "memory")

// ---- K0: qry = 0.5 * (feat_u @ W_user + b_user) ----
__global__ void qry_kernel(const float* __restrict__ feat_u,
                           const float* __restrict__ W_user,
                           const float* __restrict__ b_user) {
    int b = blockIdx.x, d = threadIdx.x;
    float acc = b_user[d];
    const float* fu = feat_u + b * DN;
#pragma unroll 8
    for (int k = 0; k < DN; k++) acc += fu[k] * W_user[k * DN + d];
    g_qry[b * DN + d] = 0.5f * acc;
}

// ---- K1: segment boundaries (seg sorted) ----
__global__ void bounds_kernel(const int* __restrict__ seg, int N, int B) {
    int g = blockIdx.x * blockDim.x + threadIdx.x;
    if (g > B) return;
    int lo = 0, hi = N;
    while (lo < hi) {
        int mid = (lo + hi) >> 1;
        if (seg[mid] < g) lo = mid + 1; else hi = mid;
    }
    g_start[g] = lo;
}

// ---- K2: persistent fused kernel ----
// 64-row tiles, double-buffered, GEMM token alternation between two
// 256-thread groups. Next-tile prep (seg/g_start ldg + qS cp.async, qS
// double-buffered) runs right after token release, hidden under the tanh
// epilogue. span==1 sum computes w in-warp (lane exp + shfl broadcast),
// eliminating the separate wS phase and one barrier.
__global__ __launch_bounds__(512, 1)
void e_kernel(const float* __restrict__ feat_i, const int* __restrict__ seg,
              const float* __restrict__ W_key, const float* __restrict__ W_e,
              int N, int tiles) {
    extern __shared__ float sm[];
    float* BS  = sm;                     // 16384: packed B fragments (x0.5)
    float* AS  = BS + 16384;             // 2 groups x 2 bufs x (64 x 132)
    float* WeS = AS + 2 * 2 * 8448;      // 128
    float* GR  = WeS + DN;

    int tid = threadIdx.x;
    int group = tid >> 8;
    int gtid = tid & 255;
    int bar = group + 1;

    // group region: eP 256 | wS 64 | red 1024 | swr 8 | segSb 2x64 | qS 2x128
    const int GRSZ = 256 + 64 + 1024 + 8 + 128 + 256;
    float* eP    = GR + group * GRSZ;
    float* wS    = eP + 256;
    float* red   = wS + 64;
    float* swr   = red + 1024;
    int*   segSb = (int*)(swr + 8);      // [2][64]
    float* qSb   = (float*)(segSb + 128);// [2][128]
    float* fsG   = AS + group * (2 * 8448);

    // ---- one-time: pack W_key fragments (tf32 rna, x0.5 folded) ----
    for (int s = tid; s < 4096; s += 512) {
        int lane_ = s & 31, pr = (s >> 5) & 1, kt = (s >> 6) & 15, cg = s >> 10;
        int gidp = lane_ >> 2, tigp = lane_ & 3;
        int n0 = cg * 32 + pr * 16 + gidp;
        int ka = kt * 8 + tigp, kb = ka + 4;
        uint4 v;
        v.x = f2tf(0.5f * W_key[ka * DN + n0]);
        v.y = f2tf(0.5f * W_key[kb * DN + n0]);
        v.z = f2tf(0.5f * W_key[ka * DN + n0 + 8]);
        v.w = f2tf(0.5f * W_key[kb * DN + n0 + 8]);
        ((uint4*)BS)[s] = v;
    }
    if (tid < DN) WeS[tid] = W_e[tid];
    __syncthreads();

    float eBias = 0.f;
#pragma unroll 8
    for (int i = 0; i < DN; i++) eBias += WeS[i];
    eBias *= 0.5f;
    int lastSeg = __ldg(&seg[N - 1]);

    unsigned fsBase  = (unsigned)__cvta_generic_to_shared(fsG);
    unsigned segBase = (unsigned)__cvta_generic_to_shared(segSb);
    unsigned qSBase  = (unsigned)__cvta_generic_to_shared(qSb);
    const float4* feat4 = (const float4*)feat_i;

    // load one 64x128 tile + its seg strip into buffer bf; always commits
    auto load_tile = [&](int t, int bf) {
        if (t < tiles) {
            int tile0 = t * TILE;
#pragma unroll
            for (int rep = 0; rep < 8; rep++) {
                int i = gtid + rep * 256;
                int r = i >> 5, c4 = i & 31;
                int node = tile0 + r;
                int ok = (node < N) ? 16 : 0;
                int nc = (node < N) ? node : (N - 1);
                const float4* src = feat4 + (size_t)nc * 32 + c4;
                unsigned dst = fsBase + (unsigned)(bf * 33792 + r * 528 + c4 * 16);
                asm volatile("cp.async.cg.shared.global [%0], [%1], 16, %2;"
                             :: "r"(dst), "l"(src), "r"(ok));
            }
            if (gtid < 16) {
                int e0 = tile0 + gtid * 4;
                if (e0 + 3 < N) {
                    const int* src = seg + e0;
                    unsigned dst = segBase + (unsigned)(bf * 256 + gtid * 16);
                    asm volatile("cp.async.ca.shared.global [%0], [%1], 16;"
                                 :: "r"(dst), "l"(src));
                }
            }
        }
        asm volatile("cp.async.commit_group;");
    };

    int w = (gtid >> 5), lane = gtid & 31, gid = lane >> 2, tig = lane & 3;
    int wm = w >> 2, wn = w & 3;
    int rowBase = wm * 32;
    int colBase = wn * 32;
    int rl8 = gtid >> 5, dq = gtid & 31;

    int lsub = lane >> 3, lr8 = lane & 7;
    unsigned aOff0 = (unsigned)((rowBase + ((lsub & 1) << 3) + lr8) * 528 +
                                ((lsub >> 1) << 4));
    unsigned aOff1 = aOff0 + 16 * 528;

    float2 we2[4];
#pragma unroll
    for (int nt = 0; nt < 4; nt++)
        we2[nt] = *(const float2*)(WeS + colBase + nt * 8 + tig * 2);

    int t0 = blockIdx.x, stride = gridDim.x;
    int step = 2 * stride;
    int myT0 = t0 + group * stride;
    int L = (tiles > t0) ? (tiles - t0 + step - 1) / step : 0;

    // prep: computes scalars for tile tn + issues its qS into buf qb; commits
    auto prep_tile = [&](int tn, int qb, int& g0o, int& spano, int& gs0o) {
        int g0n = 0, spann = 0, gs0n = 0;
        if (tn < tiles) {
            int t0n = tn * TILE;
            int nv = (N - t0n < TILE) ? (N - t0n) : TILE;
            g0n = __ldg(&seg[t0n]);
            spann = __ldg(&seg[t0n + nv - 1]) - g0n + 1;
            gs0n = __ldg(&g_start[g0n]);
            if (spann == 1 && gtid < 32) {
                const float4* src = ((const float4*)(g_qry + g0n * DN)) + gtid;
                asm volatile("cp.async.ca.shared.global [%0], [%1], 16;"
                             :: "r"(qSBase + (unsigned)(qb * 512 + gtid * 16)), "l"(src));
            }
        }
        asm volatile("cp.async.commit_group;");
        g0o = g0n; spano = spann; gs0o = gs0n;
    };

    // ---- prologue ----
    load_tile(myT0, 0);                       // commit A
    asm volatile("cp.async.wait_group 0;");   // drain A (once)
    GBAR(bar);
    int curG0, curSpan, curGs0;
    prep_tile(myT0, 0, curG0, curSpan, curGs0);  // commit qS_0
    load_tile(myT0 + step, 1);                   // commit refill(load1)

    const uint4* packU4 = (const uint4*)BS;
    float4* red4 = (float4*)red;
    int barMe = 3 + group, barPeer = 4 - group;

    for (int k = 0; k < L; k++) {
        int t = myT0 + k * step;
        bool work = (t < tiles);
        int p = k & 1;
        int tile0 = t * TILE;
        int* segS = segSb + p * 64;
        float* qS = qSb + p * 128;
        int nvalid = 0;

        if (work) {
            // drains [refill_{k-1} -> my buffer, qS_k]; leaves refill_k?? no:
            // outstanding: [refill(my buf), qS_k, refill(other)] -> keep 1
            asm volatile("cp.async.wait_group 1;");
            nvalid = (N - tile0 < TILE) ? (N - tile0) : TILE;
            bool tail = (tile0 + TILE > N);
            if (tail && gtid < TILE) {        // never taken when N%64==0
                int node = tile0 + gtid;
                if (node >= N) segS[gtid] = lastSeg;
                else if (node >= (N & ~3)) segS[gtid] = seg[node];
            }
            GBAR(bar);                        // publish tile + qS + segS
        }

        // ---- acquire tensor-pipe token ----
        if (!(group == 0 && k == 0))
            asm volatile("bar.sync %0, 512;" :: "r"(barMe) : "memory");

        float c[2][4][4];
        if (work) {
#pragma unroll
            for (int mt = 0; mt < 2; mt++)
#pragma unroll
                for (int nt = 0; nt < 4; nt++)
#pragma unroll
                    for (int q = 0; q < 4; q++) c[mt][nt][q] = 0.f;
            unsigned bufOff = (unsigned)(p * 33792);
#pragma unroll
            for (int kt = 0; kt < 16; kt++) {
                unsigned a[2][4];
                asm volatile("ldmatrix.sync.aligned.m8n8.x4.shared.b16 {%0,%1,%2,%3}, [%4];"
                             : "=r"(a[0][0]), "=r"(a[0][1]), "=r"(a[0][2]), "=r"(a[0][3])
                             : "r"(fsBase + bufOff + aOff0 + kt * 32));
                asm volatile("ldmatrix.sync.aligned.m8n8.x4.shared.b16 {%0,%1,%2,%3}, [%4];"
                             : "=r"(a[1][0]), "=r"(a[1][1]), "=r"(a[1][2]), "=r"(a[1][3])
                             : "r"(fsBase + bufOff + aOff1 + kt * 32));
#pragma unroll
                for (int pr = 0; pr < 2; pr++) {
                    uint4 b = packU4[(((wn * 16 + kt) * 2 + pr)) * 32 + lane];
                    int nt0 = pr * 2;
#pragma unroll
                    for (int mt = 0; mt < 2; mt++) {
                        asm volatile(
                            "mma.sync.aligned.m16n8k8.row.col.f32.tf32.tf32.f32 "
                            "{%0,%1,%2,%3}, {%4,%5,%6,%7}, {%8,%9}, {%0,%1,%2,%3};"
                            : "+f"(c[mt][nt0][0]), "+f"(c[mt][nt0][1]),
                              "+f"(c[mt][nt0][2]), "+f"(c[mt][nt0][3])
                            : "r"(a[mt][0]), "r"(a[mt][1]), "r"(a[mt][2]), "r"(a[mt][3]),
                              "r"(b.x), "r"(b.y));
                        asm volatile(
                            "mma.sync.aligned.m16n8k8.row.col.f32.tf32.tf32.f32 "
                            "{%0,%1,%2,%3}, {%4,%5,%6,%7}, {%8,%9}, {%0,%1,%2,%3};"
                            : "+f"(c[mt][nt0 + 1][0]), "+f"(c[mt][nt0 + 1][1]),
                              "+f"(c[mt][nt0 + 1][2]), "+f"(c[mt][nt0 + 1][3])
                            : "r"(a[mt][0]), "r"(a[mt][1]), "r"(a[mt][2]), "r"(a[mt][3]),
                              "r"(b.z), "r"(b.w));
                    }
                }
            }
        }

        // ---- release tensor-pipe token to peer ----
        if (!(group == 1 && k == L - 1))
            asm volatile("bar.arrive %0, 512;" :: "r"(barPeer) : "memory");

        if (!work) continue;

        // ---- early prep for tile t+step (qS buf 1-p); hidden under tanh ----
        int nxtG0, nxtSpan, nxtGs0;
        prep_tile(t + step, 1 - p, nxtG0, nxtSpan, nxtGs0);   // commit qS_{k+1}

        int g0 = curG0, span = curSpan, gs0 = curGs0;

        // ---- epilogue: e-partials; tanh.approx.f16x2 ----
        if (span == 1) {
            float2 qv[4];
            const float2* qp = (const float2*)(qS + colBase + tig * 2);
#pragma unroll
            for (int nt = 0; nt < 4; nt++) qv[nt] = qp[nt * 4];
#pragma unroll
            for (int mt = 0; mt < 2; mt++) {
#pragma unroll
                for (int half = 0; half < 2; half++) {
                    int row = rowBase + mt * 16 + half * 8 + gid;
                    float acc = 0.f;
#pragma unroll
                    for (int nt = 0; nt < 4; nt++) {
                        float x0 = c[mt][nt][2 * half]     + qv[nt].x;
                        float x1 = c[mt][nt][2 * half + 1] + qv[nt].y;
                        __half2 h = __floats2half2_rn(x0, x1);
                        unsigned hu = *(unsigned*)&h;
                        asm("tanh.approx.f16x2 %0, %1;" : "=r"(hu) : "r"(hu));
                        __half2 th = *(__half2*)&hu;
                        acc = fmaf(we2[nt].x, __low2float(th), acc);
                        acc = fmaf(we2[nt].y, __high2float(th), acc);
                    }
                    acc += __shfl_xor_sync(0xffffffffu, acc, 1);
                    acc += __shfl_xor_sync(0xffffffffu, acc, 2);
                    if (tig == 0) eP[wn * 64 + row] = acc;
                }
            }
            GBAR(bar);                        // eP complete

            // ---- fused sum: in-warp w (lanes 0-7 exp + shfl broadcast) ----
            const float4* fb = (const float4*)(fsG + p * 8448);
            float wlane = 0.f;
            if (lane < 8) {
                int r = rl8 + 8 * lane;
                wlane = __expf(0.5f * (eP[r] + eP[64 + r] +
                                       eP[128 + r] + eP[192 + r]) + eBias);
            }
            float wreg[8];
#pragma unroll
            for (int j = 0; j < 8; j++)
                wreg[j] = __shfl_sync(0xffffffffu, wlane, j);

            float4 a4 = make_float4(0.f, 0.f, 0.f, 0.f);
            float sw = 0.f;
#pragma unroll
            for (int j = 0; j < 8; j++) {
                int r = rl8 + 8 * j;
                if (r >= nvalid) break;
                float wv = wreg[j];
                float4 v = fb[r * 33 + dq];
                a4.x = fmaf(wv, v.x, a4.x); a4.y = fmaf(wv, v.y, a4.y);
                a4.z = fmaf(wv, v.z, a4.z); a4.w = fmaf(wv, v.w, a4.w);
                if (dq == 0) sw += wv;
            }
            red4[rl8 * 32 + dq] = a4;
            if (dq == 0) swr[rl8] = sw;
            GBAR(bar);
            if (gtid < 32) {
                float4 s = make_float4(0.f, 0.f, 0.f, 0.f);
#pragma unroll
                for (int l = 0; l < 8; l++) {
                    float4 v = red4[l * 32 + gtid];
                    s.x += v.x; s.y += v.y; s.z += v.z; s.w += v.w;
                }
                int slot = t - (gs0 / TILE);
                ((float4*)(g_acc + ((size_t)g0 * NSLOT + slot) * DN))[gtid] = s;
                if (gtid == 0)
                    g_ws[g0 * NSLOT + slot] = swr[0] + swr[1] + swr[2] + swr[3] +
                                              swr[4] + swr[5] + swr[6] + swr[7];
            }
        } else {
            // ---- rare multi-graph tile: per-row qry, wS phase ----
#pragma unroll
            for (int mt = 0; mt < 2; mt++) {
#pragma unroll
                for (int half = 0; half < 2; half++) {
                    int row = rowBase + mt * 16 + half * 8 + gid;
                    const float2* qp =
                        (const float2*)(g_qry + segS[row] * DN + colBase + tig * 2);
                    float acc = 0.f;
#pragma unroll
                    for (int nt = 0; nt < 4; nt++) {
                        float2 qv = __ldg(qp + nt * 4);
                        float x0 = c[mt][nt][2 * half]     + qv.x;
                        float x1 = c[mt][nt][2 * half + 1] + qv.y;
                        __half2 h = __floats2half2_rn(x0, x1);
                        unsigned hu = *(unsigned*)&h;
                        asm("tanh.approx.f16x2 %0, %1;" : "=r"(hu) : "r"(hu));
                        __half2 th = *(__half2*)&hu;
                        acc = fmaf(we2[nt].x, __low2float(th), acc);
                        acc = fmaf(we2[nt].y, __high2float(th), acc);
                    }
                    acc += __shfl_xor_sync(0xffffffffu, acc, 1);
                    acc += __shfl_xor_sync(0xffffffffu, acc, 2);
                    if (tig == 0) eP[wn * 64 + row] = acc;
                }
            }
            GBAR(bar);
            if (gtid < TILE)
                wS[gtid] = __expf(0.5f * (eP[gtid] + eP[64 + gtid] +
                                          eP[128 + gtid] + eP[192 + gtid]) + eBias);
            GBAR(bar);

            const float4* fb = (const float4*)(fsG + p * 8448);
            for (int j = 0; j < span; j++) {
                int gg = g0 + j;
                int gs = __ldg(&g_start[gg]);
                int rs = gs - tile0; if (rs < 0) rs = 0;
                int re = __ldg(&g_start[gg + 1]) - tile0; if (re > nvalid) re = nvalid;
                float4 a4 = make_float4(0.f, 0.f, 0.f, 0.f);
                float sw = 0.f;
                for (int r = rs + rl8; r < re; r += 8) {
                    float wv = wS[r];
                    float4 v = fb[r * 33 + dq];
                    a4.x = fmaf(wv, v.x, a4.x); a4.y = fmaf(wv, v.y, a4.y);
                    a4.z = fmaf(wv, v.z, a4.z); a4.w = fmaf(wv, v.w, a4.w);
                    if (dq == 0) sw += wv;
                }
                red4[rl8 * 32 + dq] = a4;
                if (dq == 0) swr[rl8] = sw;
                GBAR(bar);
                if (gtid < 32) {
                    float4 s = make_float4(0.f, 0.f, 0.f, 0.f);
#pragma unroll
                    for (int l = 0; l < 8; l++) {
                        float4 v = red4[l * 32 + gtid];
                        s.x += v.x; s.y += v.y; s.z += v.z; s.w += v.w;
                    }
                    int slot = t - (gs / TILE);
                    ((float4*)(g_acc + ((size_t)gg * NSLOT + slot) * DN))[gtid] = s;
                    if (gtid == 0)
                        g_ws[gg * NSLOT + slot] = swr[0] + swr[1] + swr[2] + swr[3] +
                                                  swr[4] + swr[5] + swr[6] + swr[7];
                }
                GBAR(bar);
            }
        }

        // ---- bottom: refill buf p (tile t + 2*step) ----
        load_tile(t + 2 * step, p);           // commit refill_k
        curG0 = nxtG0; curSpan = nxtSpan; curGs0 = nxtGs0;
    }
}

// ---- K3: reduce slots -> out ----
__global__ void reduce_kernel(float* __restrict__ out) {
    int g = blockIdx.x, d = threadIdx.x;
    const float* base = g_acc + (size_t)g * NSLOT * DN;
    float acc = 0.f, ws = 0.f;
#pragma unroll 8
    for (int s = 0; s < NSLOT; s++) {
        acc += base[s * DN + d];
        ws += g_ws[g * NSLOT + s];
    }
    float inv = (ws > 0.f) ? 1.f / ws : 0.f;
    out[g * DN + d] = acc * inv;
}

extern "C" void kernel_launch(void* const* d_in, const int* in_sizes, int n_in,
                              void* d_out, int out_size) {
    const float* feat_i = (const float*)d_in[0];
    const float* feat_u = (const float*)d_in[1];
    const int*   seg    = (const int*)d_in[2];
    const float* W_key  = (const float*)d_in[3];
    const float* W_user = (const float*)d_in[4];
    const float* b_user = (const float*)d_in[5];
    const float* W_e    = (const float*)d_in[6];
    float* out = (float*)d_out;

    int N = in_sizes[2];
    int B = in_sizes[1] / DN;
    int tiles = (N + TILE - 1) / TILE;

    int GRSZ = 256 + 64 + 1024 + 8 + 128 + 256;
    int smemFloats = 16384 + 2 * 2 * 8448 + DN + 2 * GRSZ;
    int smem = smemFloats * 4;
    cudaFuncSetAttribute(e_kernel, cudaFuncAttributeMaxDynamicSharedMemorySize, smem);

    qry_kernel<<<B, DN>>>(feat_u, W_user, b_user);
    bounds_kernel<<<(B + 256) / 256, 256>>>(seg, N, B);
    bounds_kernel<<<(B + 256) / 256, 256>>>(seg, N, B);  // dup: ncu capture alignment
    e_kernel<<<148, 512, smem>>>(feat_i, seg, W_key, W_e, N, tiles);
    reduce_kernel<<<B, DN>>>(out);
}

// round 16
// speedup vs baseline: 1.1422x; 1.1422x over previous
#include <cuda_runtime.h>
#include <cuda_fp16.h>
#include <math.h>
#include <stdint.h>

#define DN 128
#define TILE 64
#define NSLOT 96
#define AHSTR 272   /* fp16 A row stride in BYTES: 136 halves, 16B-aligned */

// ---- scratch (no allocations allowed) ----
__device__ float g_qry[512 * DN];   // stored pre-scaled by 0.5
__device__ int   g_start[513];
__device__ float g_acc[512 * NSLOT * DN];
__device__ float g_ws[512 * NSLOT];

#define GBAR(id) asm volatile("bar.sync %0, 256;" :: "r"(id) : "memory")

// ---- K0: qry = 0.5 * (feat_u @ W_user + b_user) ----
__global__ void qry_kernel(const float* __restrict__ feat_u,
                           const float* __restrict__ W_user,
                           const float* __restrict__ b_user) {
    int b = blockIdx.x, d = threadIdx.x;
    float acc = b_user[d];
    const float* fu = feat_u + b * DN;
#pragma unroll 8
    for (int k = 0; k < DN; k++) acc += fu[k] * W_user[k * DN + d];
    g_qry[b * DN + d] = 0.5f * acc;
}

// ---- K1: segment boundaries (seg sorted) ----
__global__ void bounds_kernel(const int* __restrict__ seg, int N, int B) {
    int g = blockIdx.x * blockDim.x + threadIdx.x;
    if (g > B) return;
    int lo = 0, hi = N;
    while (lo < hi) {
        int mid = (lo + hi) >> 1;
        if (seg[mid] < g) lo = mid + 1; else hi = mid;
    }
    g_start[g] = lo;
}

// ---- K2: persistent fused kernel, fp16 GEMM (m16n8k16, f32 accum) ----
// fp16 mantissa == tf32 mantissa -> same precision, HALF the smem port
// traffic (the measured binder: L1 ~66%). fp32 tile kept for the sum;
// converted once per tile into a per-group fp16 buffer (row stride 272 B,
// 16B-aligned for ldmatrix, conflict-free). R12 FIFO choreography.
__global__ __launch_bounds__(512, 1)
void e_kernel(const float* __restrict__ feat_i, const int* __restrict__ seg,
              const float* __restrict__ W_key, const float* __restrict__ W_e,
              int N, int tiles) {
    extern __shared__ float sm[];
    float* BS  = sm;                        // 8192 fl: packed B fp16 frags (x0.5)
    float* AS  = BS + 8192;                 // 2 groups x 2 bufs x (64 x 132) fp32
    float* AH  = AS + 2 * 2 * 8448;         // 2 groups x (64 x AHSTR bytes) fp16
    float* WeS = AH + 2 * (64 * AHSTR / 4); // 128
    float* GR  = WeS + DN;

    int tid = threadIdx.x;
    int group = tid >> 8;
    int gtid = tid & 255;
    int bar = group + 1;

    // group region: eP 256 | wS 64 | red 1024 | swr 8 | segSb 2x64 | qS 128
    const int GRSZ = 256 + 64 + 1024 + 8 + 128 + 128;
    float* eP    = GR + group * GRSZ;
    float* wS    = eP + 256;
    float* red   = wS + 64;
    float* swr   = red + 1024;
    int*   segSb = (int*)(swr + 8);         // [2][64]
    float* qS    = (float*)(segSb + 128);
    float* fsG   = AS + group * (2 * 8448);
    float* ahG   = AH + group * (64 * AHSTR / 4);

    // ---- one-time: pack B = 0.5*W_key as fp16 mma fragments ----
    // layout: [wn(4)][kt(8)][ntp(2)][lane(32)] x uint4
    //   uint4 = {b0(n even), b1(n even), b0(n odd), b1(n odd)} half2 each
    for (int s = tid; s < 2048; s += 512) {
        int lane_ = s & 31, ntp = (s >> 5) & 1, kt = (s >> 6) & 7, wn_ = s >> 9;
        int gid_ = lane_ >> 2, tig_ = lane_ & 3;
        int ne = wn_ * 32 + ntp * 16 + gid_;
        int no = ne + 8;
        int k0 = kt * 16 + tig_ * 2;
        __half2 b0e = __floats2half2_rn(0.5f * W_key[k0 * DN + ne],
                                        0.5f * W_key[(k0 + 1) * DN + ne]);
        __half2 b1e = __floats2half2_rn(0.5f * W_key[(k0 + 8) * DN + ne],
                                        0.5f * W_key[(k0 + 9) * DN + ne]);
        __half2 b0o = __floats2half2_rn(0.5f * W_key[k0 * DN + no],
                                        0.5f * W_key[(k0 + 1) * DN + no]);
        __half2 b1o = __floats2half2_rn(0.5f * W_key[(k0 + 8) * DN + no],
                                        0.5f * W_key[(k0 + 9) * DN + no]);
        uint4 v;
        v.x = *(unsigned*)&b0e; v.y = *(unsigned*)&b1e;
        v.z = *(unsigned*)&b0o; v.w = *(unsigned*)&b1o;
        ((uint4*)BS)[s] = v;
    }
    if (tid < DN) WeS[tid] = W_e[tid];
    __syncthreads();

    float eBias = 0.f;
#pragma unroll 8
    for (int i = 0; i < DN; i++) eBias += WeS[i];
    eBias *= 0.5f;
    int lastSeg = __ldg(&seg[N - 1]);

    unsigned fsBase  = (unsigned)__cvta_generic_to_shared(fsG);
    unsigned ahBase  = (unsigned)__cvta_generic_to_shared(ahG);
    unsigned segBase = (unsigned)__cvta_generic_to_shared(segSb);
    unsigned qSBase  = (unsigned)__cvta_generic_to_shared(qS);
    const float4* feat4 = (const float4*)feat_i;

    auto load_tile = [&](int t, int bf) {
        if (t < tiles) {
            int tile0 = t * TILE;
#pragma unroll
            for (int rep = 0; rep < 8; rep++) {
                int i = gtid + rep * 256;
                int r = i >> 5, c4 = i & 31;
                int node = tile0 + r;
                int ok = (node < N) ? 16 : 0;
                int nc = (node < N) ? node : (N - 1);
                const float4* src = feat4 + (size_t)nc * 32 + c4;
                unsigned dst = fsBase + (unsigned)(bf * 33792 + r * 528 + c4 * 16);
                asm volatile("cp.async.cg.shared.global [%0], [%1], 16, %2;"
                             :: "r"(dst), "l"(src), "r"(ok));
            }
            if (gtid < 16) {
                int e0 = tile0 + gtid * 4;
                if (e0 + 3 < N) {
                    const int* src = seg + e0;
                    unsigned dst = segBase + (unsigned)(bf * 256 + gtid * 16);
                    asm volatile("cp.async.ca.shared.global [%0], [%1], 16;"
                                 :: "r"(dst), "l"(src));
                }
            }
        }
        asm volatile("cp.async.commit_group;");
    };

    int w = (gtid >> 5), lane = gtid & 31, gid = lane >> 2, tig = lane & 3;
    int wm = w >> 2, wn = w & 3;
    int rowBase = wm * 32;
    int colBase = wn * 32;
    int rl8 = gtid >> 5, dq = gtid & 31;

    // ldmatrix lane address (fp16, row stride AHSTR bytes, 16B-aligned):
    // matrices [rlo,klo],[rhi,klo],[rlo,khi],[rhi,khi]
    unsigned aLane = (unsigned)((rowBase + (lane & 7) + ((lane >> 3) & 1) * 8) * AHSTR
                                + (lane >> 4) * 16);

    float2 we2[4];
#pragma unroll
    for (int nt = 0; nt < 4; nt++)
        we2[nt] = *(const float2*)(WeS + colBase + (nt >> 1) * 16 + (nt & 1) * 8 + tig * 2);

    int t0 = blockIdx.x, stride = gridDim.x;
    int step = 2 * stride;
    int myT0 = t0 + group * stride;
    int L = (tiles > t0) ? (tiles - t0 + step - 1) / step : 0;

    // prep: carried scalars + qS issue for tile tn; always commits one group
    int g0 = 0, span = 0, nvalid = 0, gs0 = 0;
    auto prep_tile = [&](int tn) {
        int g0n = 0, spann = 0, nvalidn = 0, gs0n = 0;
        if (tn < tiles) {
            int t0n = tn * TILE;
            nvalidn = (N - t0n < TILE) ? (N - t0n) : TILE;
            g0n = __ldg(&seg[t0n]);
            spann = __ldg(&seg[t0n + nvalidn - 1]) - g0n + 1;
            gs0n = __ldg(&g_start[g0n]);
            if (spann == 1 && gtid < 32) {
                const float4* src = ((const float4*)(g_qry + g0n * DN)) + gtid;
                asm volatile("cp.async.ca.shared.global [%0], [%1], 16;"
                             :: "r"(qSBase + (unsigned)(gtid * 16)), "l"(src));
            }
        }
        asm volatile("cp.async.commit_group;");
        g0 = g0n; span = spann; nvalid = nvalidn; gs0 = gs0n;
    };

    // ---- prologue ----
    load_tile(myT0, 0);                       // commit A
    asm volatile("cp.async.wait_group 0;");   // drain A (once)
    GBAR(bar);
    prep_tile(myT0);                          // commit qS_0
    load_tile(myT0 + step, 1);                // commit refill(load1)

    float4* red4 = (float4*)red;
    int barMe = 3 + group, barPeer = 4 - group;
    int cvRow = gtid >> 2, cvC = gtid & 3;

    for (int k = 0; k < L; k++) {
        int t = myT0 + k * step;
        bool work = (t < tiles);
        int p = k & 1;
        int tile0 = t * TILE;
        int* segS = segSb + p * 64;

        if (work) {
            // drains [refill -> my buffer, qS_k]; leaves the other refill
            asm volatile("cp.async.wait_group 1;");
            bool tail = (tile0 + TILE > N);
            if (tail && gtid < TILE) {        // never taken when N%64==0
                int node = tile0 + gtid;
                if (node >= N) segS[gtid] = lastSeg;
                else if (node >= (N & ~3)) segS[gtid] = seg[node];
            }
            GBAR(bar);                        // tile + qS visible

            // ---- convert fp32 tile -> fp16 buffer (hidden under peer GEMM) --
            {
                const float4* fb32 = (const float4*)(fsG + p * 8448);
#pragma unroll
                for (int j = 0; j < 8; j++) {
                    int jj = (j + 2 * cvC) & 7;       // stagger: no LDS conflicts
                    int c32 = cvC * 8 + jj;
                    float4 v = fb32[cvRow * 33 + c32];
                    __half2 h0 = __floats2half2_rn(v.x, v.y);
                    __half2 h1 = __floats2half2_rn(v.z, v.w);
                    uint2 u; u.x = *(unsigned*)&h0; u.y = *(unsigned*)&h1;
                    *(uint2*)((char*)ahG + cvRow * AHSTR + c32 * 8) = u;
                }
            }
            if (group == 0 && k == 0) GBAR(bar);   // else token sync orders AH
        }

        // ---- acquire tensor-pipe token (also orders AH for the group) ----
        if (!(group == 0 && k == 0))
            asm volatile("bar.sync %0, 512;" :: "r"(barMe) : "memory");

        float c[2][4][4];
        if (work) {
#pragma unroll
            for (int mt = 0; mt < 2; mt++)
#pragma unroll
                for (int nt = 0; nt < 4; nt++)
#pragma unroll
                    for (int q = 0; q < 4; q++) c[mt][nt][q] = 0.f;
            const uint4* packU4 = (const uint4*)BS;
#pragma unroll
            for (int kt = 0; kt < 8; kt++) {
                unsigned a[2][4];
#pragma unroll
                for (int mt = 0; mt < 2; mt++) {
                    unsigned addr = ahBase + aLane + (unsigned)(mt * 16 * AHSTR + kt * 32);
                    asm volatile("ldmatrix.sync.aligned.m8n8.x4.shared.b16 {%0,%1,%2,%3}, [%4];"
                                 : "=r"(a[mt][0]), "=r"(a[mt][1]),
                                   "=r"(a[mt][2]), "=r"(a[mt][3])
                                 : "r"(addr));
                }
#pragma unroll
                for (int ntp = 0; ntp < 2; ntp++) {
                    uint4 b = packU4[(((wn * 8 + kt) * 2 + ntp)) * 32 + lane];
                    int nt0 = ntp * 2;
#pragma unroll
                    for (int mt = 0; mt < 2; mt++) {
                        asm volatile(
                            "mma.sync.aligned.m16n8k16.row.col.f32.f16.f16.f32 "
                            "{%0,%1,%2,%3}, {%4,%5,%6,%7}, {%8,%9}, {%0,%1,%2,%3};"
                            : "+f"(c[mt][nt0][0]), "+f"(c[mt][nt0][1]),
                              "+f"(c[mt][nt0][2]), "+f"(c[mt][nt0][3])
                            : "r"(a[mt][0]), "r"(a[mt][1]), "r"(a[mt][2]), "r"(a[mt][3]),
                              "r"(b.x), "r"(b.y));
                        asm volatile(
                            "mma.sync.aligned.m16n8k16.row.col.f32.f16.f16.f32 "
                            "{%0,%1,%2,%3}, {%4,%5,%6,%7}, {%8,%9}, {%0,%1,%2,%3};"
                            : "+f"(c[mt][nt0 + 1][0]), "+f"(c[mt][nt0 + 1][1]),
                              "+f"(c[mt][nt0 + 1][2]), "+f"(c[mt][nt0 + 1][3])
                            : "r"(a[mt][0]), "r"(a[mt][1]), "r"(a[mt][2]), "r"(a[mt][3]),
                              "r"(b.z), "r"(b.w));
                    }
                }
            }
        }

        // ---- release tensor-pipe token to peer ----
        if (!(group == 1 && k == L - 1))
            asm volatile("bar.arrive %0, 512;" :: "r"(barPeer) : "memory");

        if (!work) continue;

        // ---- epilogue: e-partials; tanh.approx.f16x2 ----
        // col(nt) = colBase + (nt>>1)*16 + (nt&1)*8 + tig*2 + j
        if (span == 1) {
            float2 qv[4];
            const float2* qp = (const float2*)(qS + colBase + tig * 2);
#pragma unroll
            for (int nt = 0; nt < 4; nt++)
                qv[nt] = qp[(nt >> 1) * 8 + (nt & 1) * 4];
#pragma unroll
            for (int mt = 0; mt < 2; mt++) {
#pragma unroll
                for (int half = 0; half < 2; half++) {
                    int row = rowBase + mt * 16 + half * 8 + gid;
                    float acc = 0.f;
#pragma unroll
                    for (int nt = 0; nt < 4; nt++) {
                        float x0 = c[mt][nt][2 * half]     + qv[nt].x;
                        float x1 = c[mt][nt][2 * half + 1] + qv[nt].y;
                        __half2 h = __floats2half2_rn(x0, x1);
                        unsigned hu = *(unsigned*)&h;
                        asm("tanh.approx.f16x2 %0, %1;" : "=r"(hu) : "r"(hu));
                        __half2 th = *(__half2*)&hu;
                        acc = fmaf(we2[nt].x, __low2float(th), acc);
                        acc = fmaf(we2[nt].y, __high2float(th), acc);
                    }
                    acc += __shfl_xor_sync(0xffffffffu, acc, 1);
                    acc += __shfl_xor_sync(0xffffffffu, acc, 2);
                    if (tig == 0) eP[wn * 64 + row] = acc;
                }
            }
        } else {
#pragma unroll
            for (int mt = 0; mt < 2; mt++) {
#pragma unroll
                for (int half = 0; half < 2; half++) {
                    int row = rowBase + mt * 16 + half * 8 + gid;
                    const float2* qp =
                        (const float2*)(g_qry + segS[row] * DN + colBase + tig * 2);
                    float acc = 0.f;
#pragma unroll
                    for (int nt = 0; nt < 4; nt++) {
                        float2 qv = __ldg(qp + (nt >> 1) * 8 + (nt & 1) * 4);
                        float x0 = c[mt][nt][2 * half]     + qv.x;
                        float x1 = c[mt][nt][2 * half + 1] + qv.y;
                        __half2 h = __floats2half2_rn(x0, x1);
                        unsigned hu = *(unsigned*)&h;
                        asm("tanh.approx.f16x2 %0, %1;" : "=r"(hu) : "r"(hu));
                        __half2 th = *(__half2*)&hu;
                        acc = fmaf(we2[nt].x, __low2float(th), acc);
                        acc = fmaf(we2[nt].y, __high2float(th), acc);
                    }
                    acc += __shfl_xor_sync(0xffffffffu, acc, 1);
                    acc += __shfl_xor_sync(0xffffffffu, acc, 2);
                    if (tig == 0) eP[wn * 64 + row] = acc;
                }
            }
        }
        GBAR(bar);
        if (gtid < TILE)
            wS[gtid] = __expf(0.5f * (eP[gtid] + eP[64 + gtid] +
                                      eP[128 + gtid] + eP[192 + gtid]) + eBias);
        GBAR(bar);

        // ---- fused weighted segment-sum from the fp32 smem tile ----
        const float4* fb = (const float4*)(fsG + p * 8448);
        if (span == 1) {
            float4 a4 = make_float4(0.f, 0.f, 0.f, 0.f);
            float sw = 0.f;
#pragma unroll
            for (int r = rl8; r < TILE; r += 8) {
                if (r >= nvalid) break;
                float wv = wS[r];
                float4 v = fb[r * 33 + dq];
                a4.x = fmaf(wv, v.x, a4.x); a4.y = fmaf(wv, v.y, a4.y);
                a4.z = fmaf(wv, v.z, a4.z); a4.w = fmaf(wv, v.w, a4.w);
                if (dq == 0) sw += wv;
            }
            red4[rl8 * 32 + dq] = a4;
            if (dq == 0) swr[rl8] = sw;
            GBAR(bar);
            if (gtid < 32) {
                float4 s = make_float4(0.f, 0.f, 0.f, 0.f);
#pragma unroll
                for (int l = 0; l < 8; l++) {
                    float4 v = red4[l * 32 + gtid];
                    s.x += v.x; s.y += v.y; s.z += v.z; s.w += v.w;
                }
                int slot = t - (gs0 / TILE);
                ((float4*)(g_acc + ((size_t)g0 * NSLOT + slot) * DN))[gtid] = s;
                if (gtid == 0)
                    g_ws[g0 * NSLOT + slot] = swr[0] + swr[1] + swr[2] + swr[3] +
                                              swr[4] + swr[5] + swr[6] + swr[7];
            }
        } else {
            int g0c = g0, nvalidc = nvalid;
            for (int j = 0; j < span; j++) {
                int gg = g0c + j;
                int gs = __ldg(&g_start[gg]);
                int rs = gs - tile0; if (rs < 0) rs = 0;
                int re = __ldg(&g_start[gg + 1]) - tile0; if (re > nvalidc) re = nvalidc;
                float4 a4 = make_float4(0.f, 0.f, 0.f, 0.f);
                float sw = 0.f;
                for (int r = rs + rl8; r < re; r += 8) {
                    float wv = wS[r];
                    float4 v = fb[r * 33 + dq];
                    a4.x = fmaf(wv, v.x, a4.x); a4.y = fmaf(wv, v.y, a4.y);
                    a4.z = fmaf(wv, v.z, a4.z); a4.w = fmaf(wv, v.w, a4.w);
                    if (dq == 0) sw += wv;
                }
                red4[rl8 * 32 + dq] = a4;
                if (dq == 0) swr[rl8] = sw;
                GBAR(bar);
                if (gtid < 32) {
                    float4 s = make_float4(0.f, 0.f, 0.f, 0.f);
#pragma unroll
                    for (int l = 0; l < 8; l++) {
                        float4 v = red4[l * 32 + gtid];
                        s.x += v.x; s.y += v.y; s.z += v.z; s.w += v.w;
                    }
                    int slot = t - (gs / TILE);
                    ((float4*)(g_acc + ((size_t)gg * NSLOT + slot) * DN))[gtid] = s;
                    if (gtid == 0)
                        g_ws[gg * NSLOT + slot] = swr[0] + swr[1] + swr[2] + swr[3] +
                                                  swr[4] + swr[5] + swr[6] + swr[7];
                }
                GBAR(bar);
            }
        }

        // ---- bottom: prep tile t+step (qS commit), then refill buf p ----
        prep_tile(t + step);                  // commit qS_{k+1}
        load_tile(t + 2 * step, p);           // commit refill_k
    }
}

// ---- K3: reduce slots -> out ----
__global__ void reduce_kernel(float* __restrict__ out) {
    int g = blockIdx.x, d = threadIdx.x;
    const float* base = g_acc + (size_t)g * NSLOT * DN;
    float acc = 0.f, ws = 0.f;
#pragma unroll 8
    for (int s = 0; s < NSLOT; s++) {
        acc += base[s * DN + d];
        ws += g_ws[g * NSLOT + s];
    }
    float inv = (ws > 0.f) ? 1.f / ws : 0.f;
    out[g * DN + d] = acc * inv;
}

extern "C" void kernel_launch(void* const* d_in, const int* in_sizes, int n_in,
                              void* d_out, int out_size) {
    const float* feat_i = (const float*)d_in[0];
    const float* feat_u = (const float*)d_in[1];
    const int*   seg    = (const int*)d_in[2];
    const float* W_key  = (const float*)d_in[3];
    const float* W_user = (const float*)d_in[4];
    const float* b_user = (const float*)d_in[5];
    const float* W_e    = (const float*)d_in[6];
    float* out = (float*)d_out;

    int N = in_sizes[2];
    int B = in_sizes[1] / DN;
    int tiles = (N + TILE - 1) / TILE;

    int GRSZ = 256 + 64 + 1024 + 8 + 128 + 128;
    int smemFloats = 8192 + 2 * 2 * 8448 + 2 * (64 * AHSTR / 4) + DN + 2 * GRSZ;
    int smem = smemFloats * 4;
    cudaFuncSetAttribute(e_kernel, cudaFuncAttributeMaxDynamicSharedMemorySize, smem);

    qry_kernel<<<B, DN>>>(feat_u, W_user, b_user);
    bounds_kernel<<<(B + 256) / 256, 256>>>(seg, N, B);
    bounds_kernel<<<(B + 256) / 256, 256>>>(seg, N, B);  // dup: ncu capture alignment
    e_kernel<<<148, 512, smem>>>(feat_i, seg, W_key, W_e, N, tiles);
    reduce_kernel<<<B, DN>>>(out);
}

// round 17
// speedup vs baseline: 1.2302x; 1.0770x over previous
#include <cuda_runtime.h>
#include <cuda_fp16.h>
#include <math.h>
#include <stdint.h>

#define DN 128
#define TILE 64
#define NSLOT 96
#define AHSTR 272   /* fp16 A row stride in BYTES: 136 halves, 16B-aligned */

// ---- scratch (no allocations allowed) ----
__device__ float g_qry[512 * DN];   // stored pre-scaled by 0.5
__device__ int   g_start[513];
__device__ float g_acc[512 * NSLOT * DN];
__device__ float g_ws[512 * NSLOT];

#define GBAR(id) asm volatile("bar.sync %0, 256;" :: "r"(id) : "memory")

// ---- K0: qry = 0.5 * (feat_u @ W_user + b_user) ----
__global__ void qry_kernel(const float* __restrict__ feat_u,
                           const float* __restrict__ W_user,
                           const float* __restrict__ b_user) {
    int b = blockIdx.x, d = threadIdx.x;
    float acc = b_user[d];
    const float* fu = feat_u + b * DN;
#pragma unroll 8
    for (int k = 0; k < DN; k++) acc += fu[k] * W_user[k * DN + d];
    g_qry[b * DN + d] = 0.5f * acc;
}

// ---- K1: segment boundaries (seg sorted) ----
__global__ void bounds_kernel(const int* __restrict__ seg, int N, int B) {
    int g = blockIdx.x * blockDim.x + threadIdx.x;
    if (g > B) return;
    int lo = 0, hi = N;
    while (lo < hi) {
        int mid = (lo + hi) >> 1;
        if (seg[mid] < g) lo = mid + 1; else hi = mid;
    }
    g_start[g] = lo;
}

// ---- K2: persistent fused kernel, fp16 GEMM, register-staged tiles ----
// No fp32 smem tile: tile t+1 is LDG'd into 32 regs/thread right after
// tile t's STS (2-3k cyc of latency hiding), converted to fp16 and STS'd
// once into a single per-group AH buffer. GEMM (ldmatrix) and the weighted
// sum both read AH. cp.async carries only the 512B qS row. Token
// alternation between the two 256-thread groups unchanged.
__global__ __launch_bounds__(512, 1)
void e_kernel(const float* __restrict__ feat_i, const int* __restrict__ seg,
              const float* __restrict__ W_key, const float* __restrict__ W_e,
              int N, int tiles) {
    extern __shared__ float sm[];
    float* BS  = sm;                        // 8192 fl: packed B fp16 frags (x0.5)
    float* AH  = BS + 8192;                 // 2 groups x (64 rows x AHSTR B) fp16
    float* WeS = AH + 2 * (64 * AHSTR / 4); // 128
    float* GR  = WeS + DN;

    int tid = threadIdx.x;
    int group = tid >> 8;
    int gtid = tid & 255;
    int bar = group + 1;

    // group region: eP 256 | wS 64 | red 1024 | swr 8 | segS 64 | qS 128
    const int GRSZ = 256 + 64 + 1024 + 8 + 64 + 128;
    float* eP   = GR + group * GRSZ;
    float* wS   = eP + 256;
    float* red  = wS + 64;
    float* swr  = red + 1024;
    int*   segS = (int*)(swr + 8);          // rare span>1 path only
    float* qS   = (float*)(segS + 64);
    float* ahG  = AH + group * (64 * AHSTR / 4);

    // ---- one-time: pack B = 0.5*W_key as fp16 mma fragments ----
    // layout: [wn(4)][kt(8)][ntp(2)][lane(32)] x uint4
    for (int s = tid; s < 2048; s += 512) {
        int lane_ = s & 31, ntp = (s >> 5) & 1, kt = (s >> 6) & 7, wn_ = s >> 9;
        int gid_ = lane_ >> 2, tig_ = lane_ & 3;
        int ne = wn_ * 32 + ntp * 16 + gid_;
        int no = ne + 8;
        int k0 = kt * 16 + tig_ * 2;
        __half2 b0e = __floats2half2_rn(0.5f * W_key[k0 * DN + ne],
                                        0.5f * W_key[(k0 + 1) * DN + ne]);
        __half2 b1e = __floats2half2_rn(0.5f * W_key[(k0 + 8) * DN + ne],
                                        0.5f * W_key[(k0 + 9) * DN + ne]);
        __half2 b0o = __floats2half2_rn(0.5f * W_key[k0 * DN + no],
                                        0.5f * W_key[(k0 + 1) * DN + no]);
        __half2 b1o = __floats2half2_rn(0.5f * W_key[(k0 + 8) * DN + no],
                                        0.5f * W_key[(k0 + 9) * DN + no]);
        uint4 v;
        v.x = *(unsigned*)&b0e; v.y = *(unsigned*)&b1e;
        v.z = *(unsigned*)&b0o; v.w = *(unsigned*)&b1o;
        ((uint4*)BS)[s] = v;
    }
    if (tid < DN) WeS[tid] = W_e[tid];
    __syncthreads();

    float eBias = 0.f;
#pragma unroll 8
    for (int i = 0; i < DN; i++) eBias += WeS[i];
    eBias *= 0.5f;
    int lastSeg = __ldg(&seg[N - 1]);

    unsigned ahBase = (unsigned)__cvta_generic_to_shared(ahG);
    unsigned qSBase = (unsigned)__cvta_generic_to_shared(qS);
    const float4* feat4 = (const float4*)feat_i;

    int w = (gtid >> 5), lane = gtid & 31, gid = lane >> 2, tig = lane & 3;
    int wm = w >> 2, wn = w & 3;
    int rowBase = wm * 32;
    int colBase = wn * 32;
    int rl8 = gtid >> 5, dq = gtid & 31;
    int ldR = gtid >> 5;   // LDG/STS row base helper (i>>5 pattern reused)

    // ldmatrix lane address (fp16, row stride AHSTR, 16B-aligned)
    unsigned aLane = (unsigned)((rowBase + (lane & 7) + ((lane >> 3) & 1) * 8) * AHSTR
                                + (lane >> 4) * 16);

    float2 we2[4];
#pragma unroll
    for (int nt = 0; nt < 4; nt++)
        we2[nt] = *(const float2*)(WeS + colBase + (nt >> 1) * 16 + (nt & 1) * 8 + tig * 2);

    int t0 = blockIdx.x, stride = gridDim.x;
    int step = 2 * stride;
    int myT0 = t0 + group * stride;
    int L = (tiles > t0) ? (tiles - t0 + step - 1) / step : 0;

    // register staging of one tile (8 x float4 per thread)
    float4 stg[8];
    auto ldg_tile = [&](int t) {
        if (t < tiles) {
            int tile0 = t * TILE;
#pragma unroll
            for (int rep = 0; rep < 8; rep++) {
                int i = gtid + rep * 256;
                int r = i >> 5, c4 = i & 31;
                int node = tile0 + r;
                int nc = (node < N) ? node : (N - 1);
                stg[rep] = __ldg(feat4 + (size_t)nc * 32 + c4);
            }
        }
    };
    auto sts_tile = [&]() {
#pragma unroll
        for (int rep = 0; rep < 8; rep++) {
            int i = gtid + rep * 256;
            int r = i >> 5, c4 = i & 31;
            __half2 h0 = __floats2half2_rn(stg[rep].x, stg[rep].y);
            __half2 h1 = __floats2half2_rn(stg[rep].z, stg[rep].w);
            uint2 u; u.x = *(unsigned*)&h0; u.y = *(unsigned*)&h1;
            *(uint2*)((char*)ahG + r * AHSTR + c4 * 8) = u;
        }
    };

    // prep: carried scalars + qS cp.async for tile tn; always commits a group
    int g0 = 0, span = 0, nvalid = 0, gs0 = 0;
    auto prep_tile = [&](int tn) {
        int g0n = 0, spann = 0, nvalidn = 0, gs0n = 0;
        if (tn < tiles) {
            int t0n = tn * TILE;
            nvalidn = (N - t0n < TILE) ? (N - t0n) : TILE;
            g0n = __ldg(&seg[t0n]);
            spann = __ldg(&seg[t0n + nvalidn - 1]) - g0n + 1;
            gs0n = __ldg(&g_start[g0n]);
            if (spann == 1 && gtid < 32) {
                const float4* src = ((const float4*)(g_qry + g0n * DN)) + gtid;
                asm volatile("cp.async.ca.shared.global [%0], [%1], 16;"
                             :: "r"(qSBase + (unsigned)(gtid * 16)), "l"(src));
            }
        }
        asm volatile("cp.async.commit_group;");
        g0 = g0n; span = spann; nvalid = nvalidn; gs0 = gs0n;
    };

    // ---- prologue ----
    ldg_tile(myT0);
    prep_tile(myT0);                          // commit qS_0

    float4* red4 = (float4*)red;
    int barMe = 3 + group, barPeer = 4 - group;

    for (int k = 0; k < L; k++) {
        int t = myT0 + k * step;
        bool work = (t < tiles);
        int tile0 = t * TILE;

        if (work) {
            asm volatile("cp.async.wait_group 0;");   // qS_k landed
            if (span > 1 && gtid < TILE) {
                int node = tile0 + gtid;
                segS[gtid] = (node < N) ? seg[node] : lastSeg;
            }
            GBAR(bar);                        // qS + segS visible
            sts_tile();                       // staged regs -> fp16 AH
            ldg_tile(t + step);               // stage next tile (regs free)
            if (group == 0 && k == 0) GBAR(bar);   // order STS->ldmatrix
        }

        // ---- acquire tensor-pipe token (512-wide; orders STS for group) ----
        if (!(group == 0 && k == 0))
            asm volatile("bar.sync %0, 512;" :: "r"(barMe) : "memory");

        float c[2][4][4];
        if (work) {
#pragma unroll
            for (int mt = 0; mt < 2; mt++)
#pragma unroll
                for (int nt = 0; nt < 4; nt++)
#pragma unroll
                    for (int q = 0; q < 4; q++) c[mt][nt][q] = 0.f;
            const uint4* packU4 = (const uint4*)BS;
#pragma unroll
            for (int kt = 0; kt < 8; kt++) {
                unsigned a[2][4];
#pragma unroll
                for (int mt = 0; mt < 2; mt++) {
                    unsigned addr = ahBase + aLane + (unsigned)(mt * 16 * AHSTR + kt * 32);
                    asm volatile("ldmatrix.sync.aligned.m8n8.x4.shared.b16 {%0,%1,%2,%3}, [%4];"
                                 : "=r"(a[mt][0]), "=r"(a[mt][1]),
                                   "=r"(a[mt][2]), "=r"(a[mt][3])
                                 : "r"(addr));
                }
#pragma unroll
                for (int ntp = 0; ntp < 2; ntp++) {
                    uint4 b = packU4[(((wn * 8 + kt) * 2 + ntp)) * 32 + lane];
                    int nt0 = ntp * 2;
#pragma unroll
                    for (int mt = 0; mt < 2; mt++) {
                        asm volatile(
                            "mma.sync.aligned.m16n8k16.row.col.f32.f16.f16.f32 "
                            "{%0,%1,%2,%3}, {%4,%5,%6,%7}, {%8,%9}, {%0,%1,%2,%3};"
                            : "+f"(c[mt][nt0][0]), "+f"(c[mt][nt0][1]),
                              "+f"(c[mt][nt0][2]), "+f"(c[mt][nt0][3])
                            : "r"(a[mt][0]), "r"(a[mt][1]), "r"(a[mt][2]), "r"(a[mt][3]),
                              "r"(b.x), "r"(b.y));
                        asm volatile(
                            "mma.sync.aligned.m16n8k16.row.col.f32.f16.f16.f32 "
                            "{%0,%1,%2,%3}, {%4,%5,%6,%7}, {%8,%9}, {%0,%1,%2,%3};"
                            : "+f"(c[mt][nt0 + 1][0]), "+f"(c[mt][nt0 + 1][1]),
                              "+f"(c[mt][nt0 + 1][2]), "+f"(c[mt][nt0 + 1][3])
                            : "r"(a[mt][0]), "r"(a[mt][1]), "r"(a[mt][2]), "r"(a[mt][3]),
                              "r"(b.z), "r"(b.w));
                    }
                }
            }
        }

        // ---- release tensor-pipe token to peer ----
        if (!(group == 1 && k == L - 1))
            asm volatile("bar.arrive %0, 512;" :: "r"(barPeer) : "memory");

        if (!work) continue;

        // ---- epilogue: e-partials; tanh.approx.f16x2 ----
        // col(nt) = colBase + (nt>>1)*16 + (nt&1)*8 + tig*2 + j
        if (span == 1) {
            float2 qv[4];
            const float2* qp = (const float2*)(qS + colBase + tig * 2);
#pragma unroll
            for (int nt = 0; nt < 4; nt++)
                qv[nt] = qp[(nt >> 1) * 8 + (nt & 1) * 4];
#pragma unroll
            for (int mt = 0; mt < 2; mt++) {
#pragma unroll
                for (int half = 0; half < 2; half++) {
                    int row = rowBase + mt * 16 + half * 8 + gid;
                    float acc = 0.f;
#pragma unroll
                    for (int nt = 0; nt < 4; nt++) {
                        float x0 = c[mt][nt][2 * half]     + qv[nt].x;
                        float x1 = c[mt][nt][2 * half + 1] + qv[nt].y;
                        __half2 h = __floats2half2_rn(x0, x1);
                        unsigned hu = *(unsigned*)&h;
                        asm("tanh.approx.f16x2 %0, %1;" : "=r"(hu) : "r"(hu));
                        __half2 th = *(__half2*)&hu;
                        acc = fmaf(we2[nt].x, __low2float(th), acc);
                        acc = fmaf(we2[nt].y, __high2float(th), acc);
                    }
                    acc += __shfl_xor_sync(0xffffffffu, acc, 1);
                    acc += __shfl_xor_sync(0xffffffffu, acc, 2);
                    if (tig == 0) eP[wn * 64 + row] = acc;
                }
            }
        } else {
#pragma unroll
            for (int mt = 0; mt < 2; mt++) {
#pragma unroll
                for (int half = 0; half < 2; half++) {
                    int row = rowBase + mt * 16 + half * 8 + gid;
                    const float2* qp =
                        (const float2*)(g_qry + segS[row] * DN + colBase + tig * 2);
                    float acc = 0.f;
#pragma unroll
                    for (int nt = 0; nt < 4; nt++) {
                        float2 qv = __ldg(qp + (nt >> 1) * 8 + (nt & 1) * 4);
                        float x0 = c[mt][nt][2 * half]     + qv.x;
                        float x1 = c[mt][nt][2 * half + 1] + qv.y;
                        __half2 h = __floats2half2_rn(x0, x1);
                        unsigned hu = *(unsigned*)&h;
                        asm("tanh.approx.f16x2 %0, %1;" : "=r"(hu) : "r"(hu));
                        __half2 th = *(__half2*)&hu;
                        acc = fmaf(we2[nt].x, __low2float(th), acc);
                        acc = fmaf(we2[nt].y, __high2float(th), acc);
                    }
                    acc += __shfl_xor_sync(0xffffffffu, acc, 1);
                    acc += __shfl_xor_sync(0xffffffffu, acc, 2);
                    if (tig == 0) eP[wn * 64 + row] = acc;
                }
            }
        }
        GBAR(bar);
        if (gtid < TILE)
            wS[gtid] = __expf(0.5f * (eP[gtid] + eP[64 + gtid] +
                                      eP[128 + gtid] + eP[192 + gtid]) + eBias);
        GBAR(bar);

        // ---- fused weighted segment-sum from the fp16 AH buffer ----
        if (span == 1) {
            float4 a4 = make_float4(0.f, 0.f, 0.f, 0.f);
            float sw = 0.f;
#pragma unroll
            for (int j = 0; j < 8; j++) {
                int r = rl8 + 8 * j;
                if (r >= nvalid) break;
                float wv = wS[r];
                uint2 u = *(const uint2*)((const char*)ahG + r * AHSTR + dq * 8);
                float2 f0 = __half22float2(*(__half2*)&u.x);
                float2 f1 = __half22float2(*(__half2*)&u.y);
                a4.x = fmaf(wv, f0.x, a4.x); a4.y = fmaf(wv, f0.y, a4.y);
                a4.z = fmaf(wv, f1.x, a4.z); a4.w = fmaf(wv, f1.y, a4.w);
                if (dq == 0) sw += wv;
            }
            red4[rl8 * 32 + dq] = a4;
            if (dq == 0) swr[rl8] = sw;
            GBAR(bar);
            if (gtid < 32) {
                float4 s = make_float4(0.f, 0.f, 0.f, 0.f);
#pragma unroll
                for (int l = 0; l < 8; l++) {
                    float4 v = red4[l * 32 + gtid];
                    s.x += v.x; s.y += v.y; s.z += v.z; s.w += v.w;
                }
                int slot = t - (gs0 / TILE);
                ((float4*)(g_acc + ((size_t)g0 * NSLOT + slot) * DN))[gtid] = s;
                if (gtid == 0)
                    g_ws[g0 * NSLOT + slot] = swr[0] + swr[1] + swr[2] + swr[3] +
                                              swr[4] + swr[5] + swr[6] + swr[7];
            }
        } else {
            int g0c = g0, nvalidc = nvalid;
            for (int j = 0; j < span; j++) {
                int gg = g0c + j;
                int gs = __ldg(&g_start[gg]);
                int rs = gs - tile0; if (rs < 0) rs = 0;
                int re = __ldg(&g_start[gg + 1]) - tile0; if (re > nvalidc) re = nvalidc;
                float4 a4 = make_float4(0.f, 0.f, 0.f, 0.f);
                float sw = 0.f;
                for (int r = rs + rl8; r < re; r += 8) {
                    float wv = wS[r];
                    uint2 u = *(const uint2*)((const char*)ahG + r * AHSTR + dq * 8);
                    float2 f0 = __half22float2(*(__half2*)&u.x);
                    float2 f1 = __half22float2(*(__half2*)&u.y);
                    a4.x = fmaf(wv, f0.x, a4.x); a4.y = fmaf(wv, f0.y, a4.y);
                    a4.z = fmaf(wv, f1.x, a4.z); a4.w = fmaf(wv, f1.y, a4.w);
                    if (dq == 0) sw += wv;
                }
                red4[rl8 * 32 + dq] = a4;
                if (dq == 0) swr[rl8] = sw;
                GBAR(bar);
                if (gtid < 32) {
                    float4 s = make_float4(0.f, 0.f, 0.f, 0.f);
#pragma unroll
                    for (int l = 0; l < 8; l++) {
                        float4 v = red4[l * 32 + gtid];
                        s.x += v.x; s.y += v.y; s.z += v.z; s.w += v.w;
                    }
                    int slot = t - (gs / TILE);
                    ((float4*)(g_acc + ((size_t)gg * NSLOT + slot) * DN))[gtid] = s;
                    if (gtid == 0)
                        g_ws[gg * NSLOT + slot] = swr[0] + swr[1] + swr[2] + swr[3] +
                                                  swr[4] + swr[5] + swr[6] + swr[7];
                }
                GBAR(bar);
            }
        }

        // ---- bottom: prep tile t+step (qS commit; scalars for k+1) ----
        prep_tile(t + step);
    }
}

// ---- K3: reduce slots -> out ----
__global__ void reduce_kernel(float* __restrict__ out) {
    int g = blockIdx.x, d = threadIdx.x;
    const float* base = g_acc + (size_t)g * NSLOT * DN;
    float acc = 0.f, ws = 0.f;
#pragma unroll 8
    for (int s = 0; s < NSLOT; s++) {
        acc += base[s * DN + d];
        ws += g_ws[g * NSLOT + s];
    }
    float inv = (ws > 0.f) ? 1.f / ws : 0.f;
    out[g * DN + d] = acc * inv;
}

extern "C" void kernel_launch(void* const* d_in, const int* in_sizes, int n_in,
                              void* d_out, int out_size) {
    const float* feat_i = (const float*)d_in[0];
    const float* feat_u = (const float*)d_in[1];
    const int*   seg    = (const int*)d_in[2];
    const float* W_key  = (const float*)d_in[3];
    const float* W_user = (const float*)d_in[4];
    const float* b_user = (const float*)d_in[5];
    const float* W_e    = (const float*)d_in[6];
    float* out = (float*)d_out;

    int N = in_sizes[2];
    int B = in_sizes[1] / DN;
    int tiles = (N + TILE - 1) / TILE;

    int GRSZ = 256 + 64 + 1024 + 8 + 64 + 128;
    int smemFloats = 8192 + 2 * (64 * AHSTR / 4) + DN + 2 * GRSZ;
    int smem = smemFloats * 4;
    cudaFuncSetAttribute(e_kernel, cudaFuncAttributeMaxDynamicSharedMemorySize, smem);

    qry_kernel<<<B, DN>>>(feat_u, W_user, b_user);
    bounds_kernel<<<(B + 256) / 256, 256>>>(seg, N, B);
    bounds_kernel<<<(B + 256) / 256, 256>>>(seg, N, B);  // dup: ncu capture alignment
    e_kernel<<<148, 512, smem>>>(feat_i, seg, W_key, W_e, N, tiles);
    reduce_kernel<<<B, DN>>>(out);
}